// round 3
// baseline (speedup 1.0000x reference)
#include <cuda_runtime.h>
#include <cuda_bf16.h>
#include <cstdint>

// x[N=32768, D=2048] fp32 row-major.
// u[d] = sum_n x[n][d]^2 + eps ; out = x * rsqrt(u)

#define NROWS 32768
#define NCOLS 2048
#define NCOLS4 (NCOLS / 4)                     // 512 float4 column-groups
#define ROWS_PER_CHUNK 32
#define ROW_CHUNKS (NROWS / ROWS_PER_CHUNK)    // 1024
#define KEEP_CHUNK 640                         // chunks >= this stay L2-resident (96 MB tail)
#define SPLITS 32
#define CHUNKS_PER_SPLIT (ROW_CHUNKS / SPLITS) // 32
#define EPS 1e-6f

// Deterministic scratch (no atomics in reduction path)
__device__ float g_part [ROW_CHUNKS * NCOLS];  // 8 MB
__device__ float g_part2[SPLITS * NCOLS];      // 256 KB
__device__ float g_scale[NCOLS];               // 8 KB

// ---------------------------------------------------------------------------
// K1: per-row-chunk column sum of squares.
// grid = (2, 1024). Early chunks stream (evict-first); tail chunks cache
// normally so scale_kernel can re-read them from L2.
// ---------------------------------------------------------------------------
__global__ void __launch_bounds__(256) colsq_kernel(const float4* __restrict__ x) {
    const int cg    = blockIdx.x * 256 + threadIdx.x;   // 0..511
    const int chunk = blockIdx.y;                        // 0..1023

    const float4* p = x + (size_t)chunk * ROWS_PER_CHUNK * NCOLS4 + cg;

    float ax = 0.f, ay = 0.f, az = 0.f, aw = 0.f;
    if (chunk < KEEP_CHUNK) {
#pragma unroll 8
        for (int r = 0; r < ROWS_PER_CHUNK; ++r) {
            float4 v = __ldcs(p + (size_t)r * NCOLS4);   // streaming: don't pollute L2
            ax = fmaf(v.x, v.x, ax);
            ay = fmaf(v.y, v.y, ay);
            az = fmaf(v.z, v.z, az);
            aw = fmaf(v.w, v.w, aw);
        }
    } else {
#pragma unroll 8
        for (int r = 0; r < ROWS_PER_CHUNK; ++r) {
            float4 v = __ldg(p + (size_t)r * NCOLS4);    // tail: keep resident
            ax = fmaf(v.x, v.x, ax);
            ay = fmaf(v.y, v.y, ay);
            az = fmaf(v.z, v.z, az);
            aw = fmaf(v.w, v.w, aw);
        }
    }

    reinterpret_cast<float4*>(g_part)[(size_t)chunk * NCOLS4 + cg] =
        make_float4(ax, ay, az, aw);
}

// ---------------------------------------------------------------------------
// K2a: fold 1024 chunk-partials -> 32 split-partials. float4 across columns.
// grid = (2, 32) x 256 thr: 16384 threads, 32 float4 loads each (8 MB, L2).
// ---------------------------------------------------------------------------
__global__ void __launch_bounds__(256) reduceA_kernel() {
    const int cg    = blockIdx.x * 256 + threadIdx.x;   // 0..511
    const int split = blockIdx.y;                        // 0..31

    const float4* p = reinterpret_cast<const float4*>(g_part)
                    + (size_t)split * CHUNKS_PER_SPLIT * NCOLS4 + cg;
    float4 a = make_float4(0.f, 0.f, 0.f, 0.f);
#pragma unroll
    for (int k = 0; k < CHUNKS_PER_SPLIT; ++k) {
        float4 v = __ldcs(p + (size_t)k * NCOLS4);       // don't evict x tail
        a.x += v.x; a.y += v.y; a.z += v.z; a.w += v.w;
    }
    reinterpret_cast<float4*>(g_part2)[(size_t)split * NCOLS4 + cg] = a;
}

// ---------------------------------------------------------------------------
// K2b: fold 32 split-partials, rsqrt -> scale. 512 threads, float4.
// ---------------------------------------------------------------------------
__global__ void __launch_bounds__(256) reduceB_kernel() {
    const int cg = blockIdx.x * 256 + threadIdx.x;       // 0..511
    const float4* p = reinterpret_cast<const float4*>(g_part2) + cg;
    float4 a = make_float4(0.f, 0.f, 0.f, 0.f);
#pragma unroll
    for (int k = 0; k < SPLITS; ++k) {
        float4 v = __ldcs(p + (size_t)k * NCOLS4);
        a.x += v.x; a.y += v.y; a.z += v.z; a.w += v.w;
    }
    float4 s;
    s.x = rsqrtf(a.x + EPS);
    s.y = rsqrtf(a.y + EPS);
    s.z = rsqrtf(a.z + EPS);
    s.w = rsqrtf(a.w + EPS);
    reinterpret_cast<float4*>(g_scale)[cg] = s;
}

// ---------------------------------------------------------------------------
// K3: out = x * scale[col]. Reverse traversal to hit the L2-resident tail
// first. Streaming loads/stores (hits still hit; misses don't pollute).
// ---------------------------------------------------------------------------
#define FL4_TOTAL (NROWS * NCOLS4)             // 16M float4
#define FL4_PER_BLOCK 1024
#define K3_BLOCKS (FL4_TOTAL / FL4_PER_BLOCK)  // 16384

__global__ void __launch_bounds__(256) scale_kernel(const float4* __restrict__ x,
                                                    float4* __restrict__ out) {
    const int blk     = K3_BLOCKS - 1 - blockIdx.x;       // reversed
    const size_t base = (size_t)blk * FL4_PER_BLOCK + threadIdx.x;

#pragma unroll
    for (int it = 0; it < 4; ++it) {
        const size_t i  = base + (size_t)it * 256;
        const int    cg = (int)(i & (NCOLS4 - 1));         // NCOLS4=512 pow2

        float4 s = __ldg(reinterpret_cast<const float4*>(g_scale) + cg);
        float4 v = __ldcs(x + i);
        v.x *= s.x; v.y *= s.y; v.z *= s.z; v.w *= s.w;
        __stcs(out + i, v);
    }
}

// ---------------------------------------------------------------------------
extern "C" void kernel_launch(void* const* d_in, const int* in_sizes, int n_in,
                              void* d_out, int out_size) {
    const float4* x   = reinterpret_cast<const float4*>(d_in[0]);
    float4*       out = reinterpret_cast<float4*>(d_out);

    colsq_kernel  <<<dim3(2, ROW_CHUNKS), 256>>>(x);
    reduceA_kernel<<<dim3(2, SPLITS), 256>>>();
    reduceB_kernel<<<2, 256>>>();
    scale_kernel  <<<K3_BLOCKS, 256>>>(x, out);
}